// round 1
// baseline (speedup 1.0000x reference)
#include <cuda_runtime.h>
#include <math.h>

#define Nn 1024
#define Bb 128
#define DT 0.1f
#define STEPS 10

typedef unsigned long long u64;

// ping-pong sin/cos state, layout [j][b] (j-major, b contiguous)
__device__ float g_s[2][Nn * Bb];
__device__ float g_c[2][Nn * Bb];
// working theta, layout [i][b]
__device__ float g_th[Nn * Bb];

__device__ __forceinline__ u64 pk2(float a, float b) {
    u64 r;
    asm("mov.b64 %0, {%1, %2};" : "=l"(r) : "r"(__float_as_uint(a)), "r"(__float_as_uint(b)));
    return r;
}
__device__ __forceinline__ void up2(u64 v, float &x, float &y) {
    unsigned int a, b;
    asm("mov.b64 {%0, %1}, %2;" : "=r"(a), "=r"(b) : "l"(v));
    x = __uint_as_float(a);
    y = __uint_as_float(b);
}
__device__ __forceinline__ void fma2(u64 &d, u64 a, u64 b) {
    asm("fma.rn.f32x2 %0, %1, %2, %0;" : "+l"(d) : "l"(a), "l"(b));
}

// ---------------------------------------------------------------------------
// init: theta_init [B][N] -> g_th [i][b], g_s[0]/g_c[0] [j][b]
// ---------------------------------------------------------------------------
__global__ void kur_init(const float* __restrict__ theta_init) {
    int idx = blockIdx.x * blockDim.x + threadIdx.x;  // over N*B as i*B+b
    if (idx < Nn * Bb) {
        int i = idx / Bb;
        int b = idx - i * Bb;
        float th = theta_init[b * Nn + i];
        g_th[idx] = th;
        float sn, cs;
        __sincosf(th, &sn, &cs);
        g_s[0][idx] = sn;
        g_c[0][idx] = cs;
    }
}

// ---------------------------------------------------------------------------
// one Kuramoto step: S = K @ sin, C = K @ cos, update theta, emit new sin/cos
// block tile: BI=16 i's x BB=32 b's, j-chunk BJ=64; threads (16,8)=128
// thread tile: 2 i's x 2 b's (packed f32x2 over the b pair)
// ---------------------------------------------------------------------------
#define BI 16
#define BB 32
#define BJ 64

__global__ __launch_bounds__(128) void kur_step(
    const float* __restrict__ Kmat,
    const float* __restrict__ omega,
    const float* __restrict__ kglob,
    int rp,            // read parity (write parity = rp^1)
    int last,          // if nonzero, also write theta to out in [b][n] layout
    float* __restrict__ theta_out)
{
    __shared__ u64 Ks[BJ][BI + 1];   // K values pre-duplicated into both halves
    __shared__ u64 Ss[BJ][BB / 2];
    __shared__ u64 Cs[BJ][BB / 2];

    const int tx = threadIdx.x;          // 0..15 -> b pair
    const int ty = threadIdx.y;          // 0..7  -> i
    const int tid = ty * 16 + tx;
    const int b0 = blockIdx.x * BB;
    const int i0 = blockIdx.y * BI;

    const float* s_old = g_s[rp];
    const float* c_old = g_c[rp];
    float* s_new = g_s[rp ^ 1];
    float* c_new = g_c[rp ^ 1];

    const u64* sg = reinterpret_cast<const u64*>(s_old);
    const u64* cg = reinterpret_cast<const u64*>(c_old);

    u64 accS0 = 0, accC0 = 0, accS1 = 0, accC1 = 0;

    for (int j0 = 0; j0 < Nn; j0 += BJ) {
        __syncthreads();
        // load K tile (BI x BJ), transposed + duplicated into u64
        #pragma unroll
        for (int r = 0; r < (BI * BJ) / 128; r++) {
            int idx = r * 128 + tid;
            int ii = idx >> 6;       // / BJ
            int jj = idx & 63;       // % BJ
            float kv = Kmat[(i0 + ii) * Nn + (j0 + jj)];
            Ks[jj][ii] = pk2(kv, kv);
        }
        // load sin/cos tiles (BJ x BB) as u64 pairs
        #pragma unroll
        for (int r = 0; r < (BJ * (BB / 2)) / 128; r++) {
            int idx = r * 128 + tid;
            int jj = idx >> 4;
            int p = idx & 15;
            int g = (j0 + jj) * (Bb / 2) + (b0 / 2) + p;
            Ss[jj][p] = sg[g];
            Cs[jj][p] = cg[g];
        }
        __syncthreads();

        #pragma unroll 16
        for (int jj = 0; jj < BJ; jj++) {
            u64 k0 = Ks[jj][ty];
            u64 k1 = Ks[jj][ty + 8];
            u64 s2 = Ss[jj][tx];
            u64 c2 = Cs[jj][tx];
            fma2(accS0, k0, s2);
            fma2(accC0, k0, c2);
            fma2(accS1, k1, s2);
            fma2(accC1, k1, c2);
        }
    }

    // epilogue: 2 i's x 2 b's per thread
    const float kgn = kglob[0] * (1.0f / (float)Nn);
    float Sv[2][2], Cv[2][2];
    up2(accS0, Sv[0][0], Sv[0][1]);
    up2(accC0, Cv[0][0], Cv[0][1]);
    up2(accS1, Sv[1][0], Sv[1][1]);
    up2(accC1, Cv[1][0], Cv[1][1]);

    #pragma unroll
    for (int a = 0; a < 2; a++) {
        int i = i0 + ty + a * 8;
        float om = omega[i];
        #pragma unroll
        for (int d = 0; d < 2; d++) {
            int b = b0 + 2 * tx + d;
            int ib = i * Bb + b;
            float si = s_old[ib];
            float ci = c_old[ib];
            float coupling = ci * Sv[a][d] - si * Cv[a][d];
            float thn = g_th[ib] + DT * (om + kgn * coupling);
            float sn, cs;
            __sincosf(thn, &sn, &cs);
            float wrapped = atan2f(sn, cs);
            g_th[ib] = wrapped;
            s_new[ib] = sn;
            c_new[ib] = cs;
            if (last) theta_out[b * Nn + i] = wrapped;
        }
    }
}

// ---------------------------------------------------------------------------
// coherence: r[b] = sqrt(mean(cos)^2 + mean(sin)^2), final state in parity 0
// ---------------------------------------------------------------------------
__global__ void kur_coherence(float* __restrict__ out) {
    int b = blockIdx.x;
    int t = threadIdx.x;  // 128 threads
    const float* sf = g_s[0];
    const float* cf = g_c[0];
    float ss = 0.f, cc = 0.f;
    for (int j = t; j < Nn; j += 128) {
        ss += sf[j * Bb + b];
        cc += cf[j * Bb + b];
    }
    __shared__ float sh[2][128];
    sh[0][t] = ss;
    sh[1][t] = cc;
    __syncthreads();
    for (int o = 64; o > 0; o >>= 1) {
        if (t < o) {
            sh[0][t] += sh[0][t + o];
            sh[1][t] += sh[1][t + o];
        }
        __syncthreads();
    }
    if (t == 0) {
        float cm = sh[1][0] * (1.0f / (float)Nn);
        float sm = sh[0][0] * (1.0f / (float)Nn);
        out[b] = sqrtf(cm * cm + sm * sm);
    }
}

// ---------------------------------------------------------------------------
extern "C" void kernel_launch(void* const* d_in, const int* in_sizes, int n_in,
                              void* d_out, int out_size) {
    const float* theta_init = (const float*)d_in[0];  // [B, N]
    const float* Kmat       = (const float*)d_in[1];  // [N, N]
    const float* omega      = (const float*)d_in[2];  // [N]
    const float* kglob      = (const float*)d_in[3];  // scalar

    float* theta_out = (float*)d_out;                 // [B, N]
    float* coh_out   = (float*)d_out + (size_t)Bb * Nn;  // [B]

    kur_init<<<(Nn * Bb + 255) / 256, 256>>>(theta_init);

    dim3 grid(Bb / BB, Nn / BI);   // 4 x 64 = 256 blocks
    dim3 blk(16, 8);               // 128 threads
    for (int t = 0; t < STEPS; t++) {
        kur_step<<<grid, blk>>>(Kmat, omega, kglob, t & 1,
                                (t == STEPS - 1) ? 1 : 0, theta_out);
    }

    kur_coherence<<<Bb, 128>>>(coh_out);
}

// round 2
// speedup vs baseline: 1.9713x; 1.9713x over previous
#include <cuda_runtime.h>
#include <math.h>

#define Nn 1024
#define Bb 128
#define DT 0.1f
#define STEPS 10

#define BI 64          // i per CTA
#define BBp 32         // b-pairs per CTA (64 b)
#define CJ 32          // j chunk in smem
#define KSPLIT 16
#define BJ (Nn / KSPLIT)   // 64 j per CTA

typedef unsigned long long u64;

// ping-pong sin/cos state, layout [j][b]
__device__ float g_s[2][Nn * Bb];
__device__ float g_c[2][Nn * Bb];
// working theta (UNWRAPPED), layout [i][b]
__device__ float g_th[Nn * Bb];
// split-K partials: [kz][i][pair] as u64 (2 packed floats)
__device__ u64 g_pS[KSPLIT * Nn * (Bb / 2)];
__device__ u64 g_pC[KSPLIT * Nn * (Bb / 2)];

__device__ __forceinline__ u64 pk2(float a, float b) {
    u64 r;
    asm("mov.b64 %0, {%1, %2};" : "=l"(r) : "r"(__float_as_uint(a)), "r"(__float_as_uint(b)));
    return r;
}
__device__ __forceinline__ void up2(u64 v, float &x, float &y) {
    unsigned int a, b;
    asm("mov.b64 {%0, %1}, %2;" : "=r"(a), "=r"(b) : "l"(v));
    x = __uint_as_float(a);
    y = __uint_as_float(b);
}
__device__ __forceinline__ void fma2(u64 &d, u64 a, u64 b) {
    asm("fma.rn.f32x2 %0, %1, %2, %0;" : "+l"(d) : "l"(a), "l"(b));
}

// ---------------------------------------------------------------------------
// init: theta_init [B][N] -> g_th [i][b], g_s[0]/g_c[0] [j][b]
// ---------------------------------------------------------------------------
__global__ void kur_init(const float* __restrict__ theta_init) {
    int idx = blockIdx.x * blockDim.x + threadIdx.x;
    if (idx < Nn * Bb) {
        int i = idx / Bb;
        int b = idx - i * Bb;
        float th = theta_init[b * Nn + i];
        g_th[idx] = th;
        float sn, cs;
        __sincosf(th, &sn, &cs);
        g_s[0][idx] = sn;
        g_c[0][idx] = cs;
    }
}

// ---------------------------------------------------------------------------
// split-K GEMM: partial S = K @ sin, C = K @ cos over j in [kz*BJ, kz*BJ+BJ)
// CTA tile 64i x 64b, thread tile 4i x 4b (2 u64), 256 threads
// ---------------------------------------------------------------------------
__global__ __launch_bounds__(256) void kur_gemm(
    const float* __restrict__ Kmat, int rp)
{
    __shared__ u64 Ks[CJ][BI + 1];   // K duplicated into both f32x2 lanes
    __shared__ u64 Ss[CJ][BBp];
    __shared__ u64 Cs[CJ][BBp];

    const int tx = threadIdx.x;            // 0..15 -> pair groups tx, tx+16
    const int ty = threadIdx.y;            // 0..15 -> i group ty*4 + a
    const int tid = ty * 16 + tx;
    const int b0p = blockIdx.x * BBp;      // global pair offset
    const int i0 = blockIdx.y * BI;
    const int kz = blockIdx.z;
    const int j0 = kz * BJ;

    const u64* sg = reinterpret_cast<const u64*>(g_s[rp]);
    const u64* cg = reinterpret_cast<const u64*>(g_c[rp]);

    u64 aS[4][2] = {{0, 0}, {0, 0}, {0, 0}, {0, 0}};
    u64 aC[4][2] = {{0, 0}, {0, 0}, {0, 0}, {0, 0}};

    for (int jc = 0; jc < BJ; jc += CJ) {
        // K tile: CJ x BI = 2048 floats, 8 per thread, jj fastest (coalesced)
        #pragma unroll
        for (int r = 0; r < 8; r++) {
            int idx = r * 256 + tid;
            int ii = idx >> 5;
            int jj = idx & 31;
            float kv = Kmat[(i0 + ii) * Nn + (j0 + jc + jj)];
            Ks[jj][ii] = pk2(kv, kv);
        }
        // S/C tiles: CJ x BBp u64, 4 per thread
        #pragma unroll
        for (int r = 0; r < 4; r++) {
            int idx = r * 256 + tid;
            int jj = idx >> 5;
            int p = idx & 31;
            int g = (j0 + jc + jj) * (Bb / 2) + b0p + p;
            Ss[jj][p] = sg[g];
            Cs[jj][p] = cg[g];
        }
        __syncthreads();

        #pragma unroll 8
        for (int jj = 0; jj < CJ; jj++) {
            u64 s0 = Ss[jj][tx];
            u64 s1 = Ss[jj][tx + 16];
            u64 c0 = Cs[jj][tx];
            u64 c1 = Cs[jj][tx + 16];
            #pragma unroll
            for (int a = 0; a < 4; a++) {
                u64 k = Ks[jj][ty * 4 + a];
                fma2(aS[a][0], k, s0);
                fma2(aS[a][1], k, s1);
                fma2(aC[a][0], k, c0);
                fma2(aC[a][1], k, c1);
            }
        }
        __syncthreads();
    }

    // write partials [kz][i][pair]
    #pragma unroll
    for (int a = 0; a < 4; a++) {
        int i = i0 + ty * 4 + a;
        size_t base = (size_t)kz * (Nn * (Bb / 2)) + (size_t)i * (Bb / 2) + b0p;
        g_pS[base + tx] = aS[a][0];
        g_pS[base + tx + 16] = aS[a][1];
        g_pC[base + tx] = aC[a][0];
        g_pC[base + tx + 16] = aC[a][1];
    }
}

// ---------------------------------------------------------------------------
// reduce partials + theta update + new sin/cos (one thread per b-pair)
// ---------------------------------------------------------------------------
__global__ __launch_bounds__(256) void kur_update(
    const float* __restrict__ omega,
    const float* __restrict__ kglob,
    int rp, int last,
    float* __restrict__ theta_out)
{
    int t = blockIdx.x * 256 + threadIdx.x;    // over Nn * 64 pairs
    int i = t >> 6;
    int p = t & 63;

    float S0 = 0.f, S1 = 0.f, C0 = 0.f, C1 = 0.f;
    #pragma unroll
    for (int kz = 0; kz < KSPLIT; kz++) {
        float x, y;
        up2(g_pS[kz * (Nn * (Bb / 2)) + t], x, y);
        S0 += x; S1 += y;
        up2(g_pC[kz * (Nn * (Bb / 2)) + t], x, y);
        C0 += x; C1 += y;
    }

    const float kgn = kglob[0] * (1.0f / (float)Nn);
    const float om = omega[i];
    const int ib = i * Bb + 2 * p;

    const float* s_old = g_s[rp];
    const float* c_old = g_c[rp];
    float* s_new = g_s[rp ^ 1];
    float* c_new = g_c[rp ^ 1];

    float Sv[2] = {S0, S1}, Cv[2] = {C0, C1};
    #pragma unroll
    for (int d = 0; d < 2; d++) {
        float si = s_old[ib + d];
        float ci = c_old[ib + d];
        float coupling = ci * Sv[d] - si * Cv[d];
        float thn = g_th[ib + d] + DT * (om + kgn * coupling);
        float sn, cs;
        __sincosf(thn, &sn, &cs);
        g_th[ib + d] = thn;              // keep unwrapped (wrap commutes)
        s_new[ib + d] = sn;
        c_new[ib + d] = cs;
        if (last) {
            int b = 2 * p + d;
            theta_out[b * Nn + i] = atan2f(sn, cs);   // wrap only at output
        }
    }
}

// ---------------------------------------------------------------------------
// coherence: r[b] = sqrt(mean(cos)^2 + mean(sin)^2); final state in parity 0
// ---------------------------------------------------------------------------
__global__ void kur_coherence(float* __restrict__ out) {
    int b = blockIdx.x;
    int t = threadIdx.x;
    const float* sf = g_s[0];
    const float* cf = g_c[0];
    float ss = 0.f, cc = 0.f;
    for (int j = t; j < Nn; j += 128) {
        ss += sf[j * Bb + b];
        cc += cf[j * Bb + b];
    }
    __shared__ float sh[2][128];
    sh[0][t] = ss;
    sh[1][t] = cc;
    __syncthreads();
    for (int o = 64; o > 0; o >>= 1) {
        if (t < o) {
            sh[0][t] += sh[0][t + o];
            sh[1][t] += sh[1][t + o];
        }
        __syncthreads();
    }
    if (t == 0) {
        float cm = sh[1][0] * (1.0f / (float)Nn);
        float sm = sh[0][0] * (1.0f / (float)Nn);
        out[b] = sqrtf(cm * cm + sm * sm);
    }
}

// ---------------------------------------------------------------------------
extern "C" void kernel_launch(void* const* d_in, const int* in_sizes, int n_in,
                              void* d_out, int out_size) {
    const float* theta_init = (const float*)d_in[0];  // [B, N]
    const float* Kmat       = (const float*)d_in[1];  // [N, N]
    const float* omega      = (const float*)d_in[2];  // [N]
    const float* kglob      = (const float*)d_in[3];  // scalar

    float* theta_out = (float*)d_out;                      // [B, N]
    float* coh_out   = (float*)d_out + (size_t)Bb * Nn;    // [B]

    kur_init<<<(Nn * Bb + 255) / 256, 256>>>(theta_init);

    dim3 ggrid(Bb / (2 * BBp), Nn / BI, KSPLIT);   // 2 x 16 x 16 = 512 CTAs
    dim3 gblk(16, 16);                             // 256 threads
    int upd_blocks = (Nn * (Bb / 2)) / 256;        // 256 blocks

    for (int t = 0; t < STEPS; t++) {
        int rp = t & 1;
        kur_gemm<<<ggrid, gblk>>>(Kmat, rp);
        kur_update<<<upd_blocks, 256>>>(omega, kglob, rp,
                                        (t == STEPS - 1) ? 1 : 0, theta_out);
    }

    kur_coherence<<<Bb, 128>>>(coh_out);
}

// round 16
// speedup vs baseline: 3.3698x; 1.7094x over previous
#include <cuda_runtime.h>
#include <cuda_bf16.h>
#include <math.h>
#include <cstdint>

#define Nn 1024
#define Bb 128
#define DT 0.1f
#define STEPS 10

#define KSPLIT 4
#define KC (Nn / KSPLIT)        // 256 j per GEMM CTA
#define NCOLS 256               // 128 sin cols + 128 cos cols
#define MT 64                   // m per CTA
#define NT 64                   // n per CTA
#define KI 64                   // k per smem stage
#define SROW 72                 // padded smem row (bf16 elems): 144B, 16B-aligned

// ---------------------------------------------------------------------------
// device state
// ---------------------------------------------------------------------------
__device__ __nv_bfloat16 g_Kbf[Nn * Nn];        // K bf16, [i][j], j contiguous
__device__ __nv_bfloat16 g_scbf[NCOLS * Nn];    // B operand [n][j]: n<128 sin(b=n), else cos
__device__ float g_sf[Nn * Bb];                 // sin f32, [i][b]
__device__ float g_cf[Nn * Bb];                 // cos f32, [i][b]
__device__ float g_th[Nn * Bb];                 // theta (unwrapped), [i][b]
__device__ float g_part[KSPLIT * Nn * NCOLS];   // split-K partials [kz][i][n]

// ---------------------------------------------------------------------------
// stable-ISA tensor-core helpers (sm_80+; compiles for plain sm_103)
// ---------------------------------------------------------------------------
__device__ __forceinline__ uint32_t smem_u32(const void* p) {
    uint32_t a;
    asm("{ .reg .u64 t; cvta.to.shared.u64 t, %1; cvt.u32.u64 %0, t; }" : "=r"(a) : "l"(p));
    return a;
}
__device__ __forceinline__ void ldsm4(uint32_t &r0, uint32_t &r1, uint32_t &r2,
                                      uint32_t &r3, uint32_t a) {
    asm volatile("ldmatrix.sync.aligned.m8n8.x4.shared.b16 {%0,%1,%2,%3}, [%4];"
                 : "=r"(r0), "=r"(r1), "=r"(r2), "=r"(r3) : "r"(a));
}
__device__ __forceinline__ void mma_bf16(float* c, uint32_t a0, uint32_t a1,
                                         uint32_t a2, uint32_t a3,
                                         uint32_t b0, uint32_t b1) {
    asm volatile("mma.sync.aligned.m16n8k16.row.col.f32.bf16.bf16.f32 "
                 "{%0,%1,%2,%3}, {%4,%5,%6,%7}, {%8,%9}, {%0,%1,%2,%3};"
                 : "+f"(c[0]), "+f"(c[1]), "+f"(c[2]), "+f"(c[3])
                 : "r"(a0), "r"(a1), "r"(a2), "r"(a3), "r"(b0), "r"(b1));
}

// ---------------------------------------------------------------------------
// init kernels
// ---------------------------------------------------------------------------
__global__ void kur_init_k(const float* __restrict__ Kmat) {
    int idx = blockIdx.x * blockDim.x + threadIdx.x;
    if (idx < Nn * Nn) g_Kbf[idx] = __float2bfloat16(Kmat[idx]);
}

__global__ void kur_init_state(const float* __restrict__ theta_init) {
    int idx = blockIdx.x * blockDim.x + threadIdx.x;   // i*128 + b
    if (idx < Nn * Bb) {
        int i = idx >> 7;
        int b = idx & 127;
        float th = theta_init[b * Nn + i];
        float sn, cs;
        __sincosf(th, &sn, &cs);
        g_th[idx] = th;
        g_sf[idx] = sn;
        g_cf[idx] = cs;
        g_scbf[b * Nn + i] = __float2bfloat16(sn);
        g_scbf[(Bb + b) * Nn + i] = __float2bfloat16(cs);
    }
}

// ---------------------------------------------------------------------------
// HMMA GEMM: g_part[kz][i0:+64][n0:+64] = K[i0:+64, j0:+256] @ B[n0:+64, j0:+256]^T
// 128 threads = 4 warps; warp w owns n-subtile [n0 + 16w, +16), full m=64.
// ---------------------------------------------------------------------------
__global__ __launch_bounds__(128) void kur_gemm_mma() {
    __shared__ __nv_bfloat16 As[MT * SROW];
    __shared__ __nv_bfloat16 Bs[NT * SROW];

    const int tid = threadIdx.x;
    const int w = tid >> 5;
    const int lane = tid & 31;
    const int sel = lane >> 3;       // ldmatrix matrix index
    const int lr = lane & 7;         // ldmatrix row within matrix
    const int i0 = blockIdx.x * MT;
    const int n0 = blockIdx.y * NT;
    const int kz = blockIdx.z;
    const int j0 = kz * KC;

    const uint32_t aAs = smem_u32(As);
    const uint32_t aBs = smem_u32(Bs);

    // ldmatrix base offsets (constant per thread)
    // A matrices: row off = (sel&1)*8, col off = (sel>>1)*8
    const uint32_t aoff = (uint32_t)(((sel & 1) * 8 + lr) * SROW + (sel >> 1) * 8) * 2;
    // B matrices: row off = (sel>>1)*8, col off = (sel&1)*8
    const uint32_t boff = (uint32_t)((w * 16 + (sel >> 1) * 8 + lr) * SROW + (sel & 1) * 8) * 2;

    float acc[4][2][4];
    #pragma unroll
    for (int mf = 0; mf < 4; mf++)
        #pragma unroll
        for (int nf = 0; nf < 2; nf++)
            #pragma unroll
            for (int q = 0; q < 4; q++) acc[mf][nf][q] = 0.f;

    for (int kk = 0; kk < KC; kk += KI) {
        // stage A (64x64) and B (64x64) bf16 tiles, 16B vectors, coalesced
        const __nv_bfloat16* gA = g_Kbf + (size_t)i0 * Nn + j0 + kk;
        const __nv_bfloat16* gB = g_scbf + (size_t)n0 * Nn + j0 + kk;
        #pragma unroll
        for (int p = 0; p < 4; p++) {
            int t = p * 128 + tid;        // 0..511
            int r = t >> 3;
            int c = (t & 7) * 8;
            *(uint4*)(As + r * SROW + c) = *(const uint4*)(gA + (size_t)r * Nn + c);
            *(uint4*)(Bs + r * SROW + c) = *(const uint4*)(gB + (size_t)r * Nn + c);
        }
        __syncthreads();

        #pragma unroll
        for (int ks = 0; ks < 4; ks++) {
            const uint32_t kb = (uint32_t)(ks * 16) * 2;
            uint32_t b0, b1, b2, b3;
            ldsm4(b0, b1, b2, b3, aBs + boff + kb);
            #pragma unroll
            for (int mf = 0; mf < 4; mf++) {
                uint32_t a0, a1, a2, a3;
                ldsm4(a0, a1, a2, a3,
                      aAs + aoff + kb + (uint32_t)(mf * 16 * SROW) * 2);
                mma_bf16(acc[mf][0], a0, a1, a2, a3, b0, b1);
                mma_bf16(acc[mf][1], a0, a1, a2, a3, b2, b3);
            }
        }
        __syncthreads();
    }

    // epilogue: write f32 partials [kz][i][n]
    const int g = lane >> 2;
    const int q = lane & 3;
    float* base = g_part + (size_t)kz * Nn * NCOLS;
    #pragma unroll
    for (int mf = 0; mf < 4; mf++) {
        int row0 = i0 + mf * 16 + g;
        #pragma unroll
        for (int nf = 0; nf < 2; nf++) {
            int nc = n0 + w * 16 + nf * 8 + q * 2;
            *(float2*)(base + (size_t)row0 * NCOLS + nc) =
                make_float2(acc[mf][nf][0], acc[mf][nf][1]);
            *(float2*)(base + (size_t)(row0 + 8) * NCOLS + nc) =
                make_float2(acc[mf][nf][2], acc[mf][nf][3]);
        }
    }
}

// ---------------------------------------------------------------------------
// update: reduce partials, theta step, sincos, write f32 + bf16 (transposed)
// block tile 32 i x 32 b, 256 threads x 4 elements
// ---------------------------------------------------------------------------
__global__ __launch_bounds__(256) void kur_update(
    const float* __restrict__ omega,
    const float* __restrict__ kglob,
    int last,
    float* __restrict__ theta_out)
{
    __shared__ __nv_bfloat16 tS[32][33];
    __shared__ __nv_bfloat16 tC[32][33];
    __shared__ float tW[32][33];

    const int b0 = blockIdx.x * 32;
    const int i0 = blockIdx.y * 32;
    const int tid = threadIdx.x;
    const float kgn = kglob[0] * (1.0f / (float)Nn);

    #pragma unroll
    for (int k = 0; k < 4; k++) {
        int e = k * 256 + tid;
        int ii = e >> 5;
        int bb = e & 31;
        int i = i0 + ii;
        int b = b0 + bb;

        float S = 0.f, C = 0.f;
        #pragma unroll
        for (int kz = 0; kz < KSPLIT; kz++) {
            size_t base = ((size_t)kz * Nn + i) * NCOLS;
            S += g_part[base + b];
            C += g_part[base + Bb + b];
        }
        int ib = i * Bb + b;
        float si = g_sf[ib];
        float ci = g_cf[ib];
        float coupling = ci * S - si * C;
        float thn = g_th[ib] + DT * (omega[i] + kgn * coupling);
        float sn, cs;
        __sincosf(thn, &sn, &cs);
        g_th[ib] = thn;          // stays unwrapped; wrap commutes
        g_sf[ib] = sn;
        g_cf[ib] = cs;
        tS[ii][bb] = __float2bfloat16(sn);
        tC[ii][bb] = __float2bfloat16(cs);
        if (last) tW[ii][bb] = atan2f(sn, cs);
    }
    __syncthreads();

    #pragma unroll
    for (int k = 0; k < 4; k++) {
        int e = k * 256 + tid;
        int bb = e >> 5;
        int ii = e & 31;
        g_scbf[(b0 + bb) * Nn + i0 + ii] = tS[ii][bb];
        g_scbf[(Bb + b0 + bb) * Nn + i0 + ii] = tC[ii][bb];
        if (last) theta_out[(b0 + bb) * Nn + i0 + ii] = tW[ii][bb];
    }
}

// ---------------------------------------------------------------------------
// coherence from final f32 state ([i][b] layout)
// ---------------------------------------------------------------------------
__global__ void kur_coherence(float* __restrict__ out) {
    int b = blockIdx.x;
    int t = threadIdx.x;
    float ss = 0.f, cc = 0.f;
    for (int i = t; i < Nn; i += 128) {
        ss += g_sf[i * Bb + b];
        cc += g_cf[i * Bb + b];
    }
    __shared__ float sh[2][128];
    sh[0][t] = ss;
    sh[1][t] = cc;
    __syncthreads();
    for (int o = 64; o > 0; o >>= 1) {
        if (t < o) {
            sh[0][t] += sh[0][t + o];
            sh[1][t] += sh[1][t + o];
        }
        __syncthreads();
    }
    if (t == 0) {
        float cm = sh[1][0] * (1.0f / (float)Nn);
        float sm = sh[0][0] * (1.0f / (float)Nn);
        out[b] = sqrtf(cm * cm + sm * sm);
    }
}

// ---------------------------------------------------------------------------
extern "C" void kernel_launch(void* const* d_in, const int* in_sizes, int n_in,
                              void* d_out, int out_size) {
    const float* theta_init = (const float*)d_in[0];  // [B, N]
    const float* Kmat       = (const float*)d_in[1];  // [N, N]
    const float* omega      = (const float*)d_in[2];  // [N]
    const float* kglob      = (const float*)d_in[3];  // scalar

    float* theta_out = (float*)d_out;                     // [B, N]
    float* coh_out   = (float*)d_out + (size_t)Bb * Nn;   // [B]

    kur_init_k<<<(Nn * Nn + 255) / 256, 256>>>(Kmat);
    kur_init_state<<<(Nn * Bb + 255) / 256, 256>>>(theta_init);

    dim3 ggrid(Nn / MT, NCOLS / NT, KSPLIT);   // 16 x 4 x 4 = 256 CTAs
    dim3 ugrid(Bb / 32, Nn / 32);              // 4 x 32 = 128 CTAs

    for (int t = 0; t < STEPS; t++) {
        kur_gemm_mma<<<ggrid, 128>>>();
        kur_update<<<ugrid, 256>>>(omega, kglob,
                                   (t == STEPS - 1) ? 1 : 0, theta_out);
    }

    kur_coherence<<<Bb, 128>>>(coh_out);
}